// round 1
// baseline (speedup 1.0000x reference)
#include <cuda_runtime.h>

#define APB 256      // anchors per block == threads per block
#define NANN 32
#define NC 80
#define MAXB 16

__device__ float g_acc[MAXB * 3];   // per image: cls_sum, reg_sum, num_pos

__global__ void zero_acc_kernel() {
    if (threadIdx.x < MAXB * 3) g_acc[threadIdx.x] = 0.0f;
}

__global__ __launch_bounds__(APB) void focal_main_kernel(
    const float* __restrict__ cls,     // [B,K,C]
    const float* __restrict__ regs,    // [B,K,4]
    const float* __restrict__ anc,     // [1,K,4]
    const float* __restrict__ ann,     // [B,NANN,5]
    int K)
{
    const int b   = blockIdx.y;
    const int s   = blockIdx.x * APB;   // first anchor of this block
    const int tid = threadIdx.x;

    __shared__ float s_ann[NANN * 5];
    __shared__ float s_area[NANN];
    __shared__ int   s_state[APB];      // -2 ignore, -1 negative, >=0 positive class
    __shared__ float s_red[3][APB / 32];

    if (tid < NANN * 5) s_ann[tid] = ann[(size_t)b * NANN * 5 + tid];
    __syncthreads();
    if (tid < NANN) {
        float x1 = s_ann[tid*5+0], y1 = s_ann[tid*5+1];
        float x2 = s_ann[tid*5+2], y2 = s_ann[tid*5+3];
        s_area[tid] = (x2 - x1) * (y2 - y1);
    }
    __syncthreads();

    float reg_sum = 0.0f;
    float npos    = 0.0f;
    int   state   = -2;
    const int k   = s + tid;

    if (k < K) {
        const float ax1 = anc[4*(size_t)k+0], ay1 = anc[4*(size_t)k+1];
        const float ax2 = anc[4*(size_t)k+2], ay2 = anc[4*(size_t)k+3];
        const float area_a = (ax2 - ax1) * (ay2 - ay1);

        float best = -1e30f;
        int   bi   = 0;
        #pragma unroll
        for (int n = 0; n < NANN; n++) {
            const float bx1 = s_ann[n*5+0], by1 = s_ann[n*5+1];
            const float bx2 = s_ann[n*5+2], by2 = s_ann[n*5+3];
            const float lbl = s_ann[n*5+4];
            float iw = fmaxf(fminf(ax2, bx2) - fmaxf(ax1, bx1), 0.0f);
            float ih = fmaxf(fminf(ay2, by2) - fmaxf(ay1, by1), 0.0f);
            float inter = iw * ih;
            float uni   = fmaxf(area_a + s_area[n] - inter, 1e-8f);
            float iou   = inter / uni;
            if (lbl < 0.0f) iou = -1.0f;     // padding annotations
            if (iou > best) { best = iou; bi = n; }   // strict > == first-argmax
        }

        if (best >= 0.5f) {
            state = (int)s_ann[bi*5+4];
            npos  = 1.0f;
            // regression smooth-L1 for this positive anchor
            const float aw  = ax2 - ax1, ah = ay2 - ay1;
            const float acx = ax1 + 0.5f * aw, acy = ay1 + 0.5f * ah;
            const float gx1 = s_ann[bi*5+0], gy1 = s_ann[bi*5+1];
            const float gx2 = s_ann[bi*5+2], gy2 = s_ann[bi*5+3];
            const float gw  = fmaxf(gx2 - gx1, 1.0f);
            const float gh  = fmaxf(gy2 - gy1, 1.0f);
            const float gcx = gx1 + 0.5f * gw, gcy = gy1 + 0.5f * gh;
            float t0 = (gcx - acx) / aw * 10.0f;
            float t1 = (gcy - acy) / ah * 10.0f;
            float t2 = __logf(gw / aw) * 5.0f;
            float t3 = __logf(gh / ah) * 5.0f;
            const float4 r = *(const float4*)(regs + ((size_t)b * K + k) * 4);
            float d0 = fabsf(t0 - r.x), d1 = fabsf(t1 - r.y);
            float d2 = fabsf(t2 - r.z), d3 = fabsf(t3 - r.w);
            const float th = 1.0f / 9.0f, off = 0.5f / 9.0f;
            reg_sum += (d0 <= th) ? 4.5f * d0 * d0 : d0 - off;
            reg_sum += (d1 <= th) ? 4.5f * d1 * d1 : d1 - off;
            reg_sum += (d2 <= th) ? 4.5f * d2 * d2 : d2 - off;
            reg_sum += (d3 <= th) ? 4.5f * d3 * d3 : d3 - off;
        } else {
            state = (best < 0.4f) ? -1 : -2;
        }
    }
    s_state[tid] = state;
    __syncthreads();

    // ---- classification loss: fully coalesced float4 sweep over [APB x NC] ----
    float cls_sum = 0.0f;
    const float4* cp = (const float4*)(cls + (size_t)b * K * NC);
    const int C4 = NC / 4;  // 20 float4 per anchor
    #pragma unroll
    for (int it = 0; it < APB * C4 / APB; it++) {   // 20 iterations
        const int rel = it * APB + tid;
        const int al  = rel / C4;         // local anchor 0..255
        const int c4  = rel % C4;
        const int k2  = s + al;
        if (k2 < K) {
            const int st = s_state[al];
            if (st != -2) {
                const float4 v = cp[(size_t)k2 * C4 + c4];
                const int cbase = c4 * 4;
                const float pv[4] = {v.x, v.y, v.z, v.w};
                #pragma unroll
                for (int j = 0; j < 4; j++) {
                    float p = fminf(fmaxf(pv[j], 1e-4f), 1.0f - 1e-4f);
                    const bool pos = (st == cbase + j);
                    const float q = pos ? (1.0f - p) : p;
                    const float a = pos ? 0.25f : 0.75f;
                    // a * sqrt(q) * (-log(1-q)) covers both branches
                    cls_sum += a * __fsqrt_rn(q) * (-__logf(1.0f - q));
                }
            }
        }
    }

    // ---- block reduction of (cls_sum, reg_sum, npos) ----
    #pragma unroll
    for (int o = 16; o > 0; o >>= 1) {
        cls_sum += __shfl_down_sync(0xffffffffu, cls_sum, o);
        reg_sum += __shfl_down_sync(0xffffffffu, reg_sum, o);
        npos    += __shfl_down_sync(0xffffffffu, npos, o);
    }
    const int w = tid >> 5, l = tid & 31;
    if (l == 0) { s_red[0][w] = cls_sum; s_red[1][w] = reg_sum; s_red[2][w] = npos; }
    __syncthreads();
    if (tid == 0) {
        float c = 0.0f, r = 0.0f, n = 0.0f;
        #pragma unroll
        for (int i = 0; i < APB / 32; i++) { c += s_red[0][i]; r += s_red[1][i]; n += s_red[2][i]; }
        atomicAdd(&g_acc[b*3+0], c);
        atomicAdd(&g_acc[b*3+1], r);
        atomicAdd(&g_acc[b*3+2], n);
    }
}

__global__ void finalize_kernel(float* __restrict__ out, int B) {
    if (threadIdx.x == 0 && blockIdx.x == 0) {
        float cs = 0.0f, rs = 0.0f;
        for (int b = 0; b < B; b++) {
            const float np = g_acc[b*3+2];
            cs += g_acc[b*3+0] / fmaxf(np, 1.0f);
            rs += (np > 0.0f) ? g_acc[b*3+1] / fmaxf(np * 4.0f, 1.0f) : 0.0f;
        }
        out[0] = cs / (float)B;
        out[1] = rs / (float)B;
    }
}

extern "C" void kernel_launch(void* const* d_in, const int* in_sizes, int n_in,
                              void* d_out, int out_size) {
    const float* cls  = (const float*)d_in[0];   // [B,K,C]
    const float* regs = (const float*)d_in[1];   // [B,K,4]
    const float* anc  = (const float*)d_in[2];   // [1,K,4]
    const float* ann  = (const float*)d_in[3];   // [B,NANN,5]

    const int K = in_sizes[2] / 4;
    const int B = in_sizes[3] / (NANN * 5);

    zero_acc_kernel<<<1, MAXB * 3>>>();
    dim3 grid((K + APB - 1) / APB, B);
    focal_main_kernel<<<grid, APB>>>(cls, regs, anc, ann, K);
    finalize_kernel<<<1, 32>>>((float*)d_out, B);
}

// round 2
// speedup vs baseline: 2.1703x; 2.1703x over previous
#include <cuda_runtime.h>

#define APB 256      // anchors per block == threads per block
#define NANN 32
#define NC 80
#define C4N (NC / 4) // 20 float4 per anchor
#define MAXB 16

__device__ float g_acc[MAXB * 3];        // per image: cls_sum, reg_sum, num_pos
__device__ unsigned int g_count = 0;     // completed-block counter (self-resetting)

__device__ __forceinline__ float fsqrt_approx(float x) {
    float r;
    asm("sqrt.approx.f32 %0, %1;" : "=f"(r) : "f"(x));
    return r;
}
__device__ __forceinline__ float flg2_approx(float x) {
    float r;
    asm("lg2.approx.f32 %0, %1;" : "=f"(r) : "f"(x));
    return r;
}

__global__ __launch_bounds__(APB) void focal_fused_kernel(
    const float* __restrict__ cls,     // [B,K,C]
    const float* __restrict__ regs,    // [B,K,4]
    const float* __restrict__ anc,     // [1,K,4]
    const float* __restrict__ ann,     // [B,NANN,5]
    float* __restrict__ out,
    int K, int B)
{
    const int b   = blockIdx.y;
    const int s   = blockIdx.x * APB;
    const int tid = threadIdx.x;

    __shared__ float s_ann[NANN * 5];
    __shared__ float s_area[NANN];
    __shared__ int   s_state[APB];      // -2 ignore, -1 negative, >=0 positive class
    __shared__ float s_red[3][APB / 32];

    if (tid < NANN * 5) s_ann[tid] = ann[(size_t)b * NANN * 5 + tid];
    __syncthreads();
    if (tid < NANN) {
        float x1 = s_ann[tid*5+0], y1 = s_ann[tid*5+1];
        float x2 = s_ann[tid*5+2], y2 = s_ann[tid*5+3];
        s_area[tid] = (x2 - x1) * (y2 - y1);
    }
    __syncthreads();

    float reg_sum = 0.0f;
    float npos    = 0.0f;
    int   state   = -2;
    const int k   = s + tid;

    if (k < K) {
        const float4 av = *(const float4*)(anc + 4*(size_t)k);
        const float ax1 = av.x, ay1 = av.y, ax2 = av.z, ay2 = av.w;
        const float area_a = (ax2 - ax1) * (ay2 - ay1);

        float best = -1e30f;
        int   bi   = 0;
        for (int n = 0; n < NANN; n++) {
            const float bx1 = s_ann[n*5+0], by1 = s_ann[n*5+1];
            const float bx2 = s_ann[n*5+2], by2 = s_ann[n*5+3];
            const float lbl = s_ann[n*5+4];
            float iw = fmaxf(fminf(ax2, bx2) - fmaxf(ax1, bx1), 0.0f);
            float ih = fmaxf(fminf(ay2, by2) - fmaxf(ay1, by1), 0.0f);
            float inter = iw * ih;
            float uni   = fmaxf(area_a + s_area[n] - inter, 1e-8f);
            float iou   = inter / uni;
            if (lbl < 0.0f) iou = -1.0f;
            if (iou > best) { best = iou; bi = n; }   // strict > == first-argmax
        }

        if (best >= 0.5f) {
            state = (int)s_ann[bi*5+4];
            npos  = 1.0f;
            const float aw  = ax2 - ax1, ah = ay2 - ay1;
            const float acx = ax1 + 0.5f * aw, acy = ay1 + 0.5f * ah;
            const float gx1 = s_ann[bi*5+0], gy1 = s_ann[bi*5+1];
            const float gx2 = s_ann[bi*5+2], gy2 = s_ann[bi*5+3];
            const float gw  = fmaxf(gx2 - gx1, 1.0f);
            const float gh  = fmaxf(gy2 - gy1, 1.0f);
            const float gcx = gx1 + 0.5f * gw, gcy = gy1 + 0.5f * gh;
            float t0 = (gcx - acx) / aw * 10.0f;
            float t1 = (gcy - acy) / ah * 10.0f;
            float t2 = __logf(gw / aw) * 5.0f;
            float t3 = __logf(gh / ah) * 5.0f;
            const float4 r = *(const float4*)(regs + ((size_t)b * K + k) * 4);
            float d0 = fabsf(t0 - r.x), d1 = fabsf(t1 - r.y);
            float d2 = fabsf(t2 - r.z), d3 = fabsf(t3 - r.w);
            const float th = 1.0f / 9.0f, off = 0.5f / 9.0f;
            reg_sum += (d0 <= th) ? 4.5f * d0 * d0 : d0 - off;
            reg_sum += (d1 <= th) ? 4.5f * d1 * d1 : d1 - off;
            reg_sum += (d2 <= th) ? 4.5f * d2 * d2 : d2 - off;
            reg_sum += (d3 <= th) ? 4.5f * d3 * d3 : d3 - off;
        } else {
            state = (best < 0.4f) ? -1 : -2;
        }
    }
    s_state[tid] = state;
    __syncthreads();

    // ---- classification loss: coalesced float4 sweep over [APB x NC] ----
    // term = a * sqrt(q) * (-log(1-q)) with q = pos ? 1-p : p, a = pos ? .25 : .75
    //      = coef * sqrt(q) * lg2(1-q),  coef = -(a*ln2)
    const float LN2 = 0.6931471805599453f;
    const float COEF_NEG = -0.75f * LN2;
    const float COEF_POS = -0.25f * LN2;

    float cls_sum = 0.0f;
    const float4* cp = (const float4*)(cls + (size_t)b * K * NC);
    #pragma unroll 4
    for (int it = 0; it < C4N; it++) {
        const int rel = it * APB + tid;
        const int al  = rel / C4N;
        const int c4  = rel % C4N;
        const int k2  = s + al;
        if (k2 < K) {
            const int st = s_state[al];
            if (st != -2) {
                const float4 v = cp[(size_t)k2 * C4N + c4];
                const int cbase = c4 * 4;
                const float pv[4] = {v.x, v.y, v.z, v.w};
                #pragma unroll
                for (int j = 0; j < 4; j++) {
                    float p = fminf(fmaxf(pv[j], 1e-4f), 1.0f - 1e-4f);
                    const bool pos = (st == cbase + j);
                    const float q    = pos ? (1.0f - p) : p;
                    const float coef = pos ? COEF_POS : COEF_NEG;
                    cls_sum = fmaf(coef * fsqrt_approx(q), flg2_approx(1.0f - q), cls_sum);
                }
            }
        }
    }

    // ---- block reduction ----
    #pragma unroll
    for (int o = 16; o > 0; o >>= 1) {
        cls_sum += __shfl_down_sync(0xffffffffu, cls_sum, o);
        reg_sum += __shfl_down_sync(0xffffffffu, reg_sum, o);
        npos    += __shfl_down_sync(0xffffffffu, npos, o);
    }
    const int w = tid >> 5, l = tid & 31;
    if (l == 0) { s_red[0][w] = cls_sum; s_red[1][w] = reg_sum; s_red[2][w] = npos; }
    __syncthreads();

    if (tid == 0) {
        float c = 0.0f, r = 0.0f, n = 0.0f;
        #pragma unroll
        for (int i = 0; i < APB / 32; i++) { c += s_red[0][i]; r += s_red[1][i]; n += s_red[2][i]; }
        atomicAdd(&g_acc[b*3+0], c);
        atomicAdd(&g_acc[b*3+1], r);
        atomicAdd(&g_acc[b*3+2], n);
        __threadfence();

        const unsigned int total = gridDim.x * gridDim.y;
        const unsigned int old = atomicAdd(&g_count, 1u);
        if (old == total - 1u) {
            // last block: finalize, write output, reset accumulators for next replay
            float cs = 0.0f, rs = 0.0f;
            for (int bb = 0; bb < B; bb++) {
                const float acc_c = atomicAdd(&g_acc[bb*3+0], 0.0f);
                const float acc_r = atomicAdd(&g_acc[bb*3+1], 0.0f);
                const float np    = atomicAdd(&g_acc[bb*3+2], 0.0f);
                cs += acc_c / fmaxf(np, 1.0f);
                rs += (np > 0.0f) ? acc_r / fmaxf(np * 4.0f, 1.0f) : 0.0f;
            }
            out[0] = cs / (float)B;
            out[1] = rs / (float)B;
            for (int i = 0; i < B * 3; i++) g_acc[i] = 0.0f;
            __threadfence();
            g_count = 0u;
            __threadfence();
        }
    }
}

extern "C" void kernel_launch(void* const* d_in, const int* in_sizes, int n_in,
                              void* d_out, int out_size) {
    const float* cls  = (const float*)d_in[0];   // [B,K,C]
    const float* regs = (const float*)d_in[1];   // [B,K,4]
    const float* anc  = (const float*)d_in[2];   // [1,K,4]
    const float* ann  = (const float*)d_in[3];   // [B,NANN,5]

    const int K = in_sizes[2] / 4;
    const int B = in_sizes[3] / (NANN * 5);

    dim3 grid((K + APB - 1) / APB, B);
    focal_fused_kernel<<<grid, APB>>>(cls, regs, anc, ann, (float*)d_out, K, B);
}

// round 3
// speedup vs baseline: 2.5163x; 1.1594x over previous
#include <cuda_runtime.h>

#define APB 256      // anchors per block == threads per block
#define NANN 32
#define NC 80
#define C4N (NC / 4) // 20 float4 per anchor
#define MAXB 16

__device__ float g_acc[MAXB * 3];        // per image: cls_sum, reg_sum, num_pos
__device__ unsigned int g_count = 0;     // completed-block counter (self-resetting)

__device__ __forceinline__ float fsqrt_approx(float x) {
    float r;
    asm("sqrt.approx.f32 %0, %1;" : "=f"(r) : "f"(x));
    return r;
}
__device__ __forceinline__ float flg2_approx(float x) {
    float r;
    asm("lg2.approx.f32 %0, %1;" : "=f"(r) : "f"(x));
    return r;
}

__global__ __launch_bounds__(APB) void focal_fused_kernel(
    const float* __restrict__ cls,     // [B,K,C]
    const float* __restrict__ regs,    // [B,K,4]
    const float* __restrict__ anc,     // [1,K,4]
    const float* __restrict__ ann,     // [B,NANN,5]
    float* __restrict__ out,
    int K, int B)
{
    const int b   = blockIdx.y;
    const int s   = blockIdx.x * APB;
    const int tid = threadIdx.x;

    __shared__ float s_ann[NANN * 5];
    __shared__ float s_area[NANN];
    __shared__ float s_w[APB];          // per-anchor sweep weight: 0 or -0.75*ln2
    __shared__ float s_red[3][APB / 32];

    if (tid < NANN * 5) s_ann[tid] = ann[(size_t)b * NANN * 5 + tid];
    __syncthreads();
    if (tid < NANN) {
        float x1 = s_ann[tid*5+0], y1 = s_ann[tid*5+1];
        float x2 = s_ann[tid*5+2], y2 = s_ann[tid*5+3];
        s_area[tid] = (x2 - x1) * (y2 - y1);
    }
    __syncthreads();

    const float LN2      = 0.6931471805599453f;
    const float COEF_NEG = -0.75f * LN2;   // for term = COEF * sqrt(p) * lg2(1-p)
    const float COEF_POS = -0.25f * LN2;

    float reg_sum = 0.0f;
    float npos    = 0.0f;
    float cls_sum = 0.0f;     // starts with positive-anchor correction
    const int k   = s + tid;

    {
        int   state = -2;     // -2 ignore/invalid, -1 negative, >=0 positive class
        if (k < K) {
            const float4 av = *(const float4*)(anc + 4*(size_t)k);
            const float ax1 = av.x, ay1 = av.y, ax2 = av.z, ay2 = av.w;
            const float area_a = (ax2 - ax1) * (ay2 - ay1);

            float best = -1e30f;
            int   bi   = 0;
            for (int n = 0; n < NANN; n++) {
                const float bx1 = s_ann[n*5+0], by1 = s_ann[n*5+1];
                const float bx2 = s_ann[n*5+2], by2 = s_ann[n*5+3];
                const float lbl = s_ann[n*5+4];
                float iw = fmaxf(fminf(ax2, bx2) - fmaxf(ax1, bx1), 0.0f);
                float ih = fmaxf(fminf(ay2, by2) - fmaxf(ay1, by1), 0.0f);
                float inter = iw * ih;
                float uni   = fmaxf(area_a + s_area[n] - inter, 1e-8f);
                float iou   = inter / uni;
                if (lbl < 0.0f) iou = -1.0f;
                if (iou > best) { best = iou; bi = n; }   // strict > == first-argmax
            }

            if (best >= 0.5f) {
                state = (int)s_ann[bi*5+4];
                npos  = 1.0f;
                const float aw  = ax2 - ax1, ah = ay2 - ay1;
                const float acx = ax1 + 0.5f * aw, acy = ay1 + 0.5f * ah;
                const float gx1 = s_ann[bi*5+0], gy1 = s_ann[bi*5+1];
                const float gx2 = s_ann[bi*5+2], gy2 = s_ann[bi*5+3];
                const float gw  = fmaxf(gx2 - gx1, 1.0f);
                const float gh  = fmaxf(gy2 - gy1, 1.0f);
                const float gcx = gx1 + 0.5f * gw, gcy = gy1 + 0.5f * gh;
                float t0 = (gcx - acx) / aw * 10.0f;
                float t1 = (gcy - acy) / ah * 10.0f;
                float t2 = __logf(gw / aw) * 5.0f;
                float t3 = __logf(gh / ah) * 5.0f;
                const float4 r = *(const float4*)(regs + ((size_t)b * K + k) * 4);
                float d0 = fabsf(t0 - r.x), d1 = fabsf(t1 - r.y);
                float d2 = fabsf(t2 - r.z), d3 = fabsf(t3 - r.w);
                const float th = 1.0f / 9.0f, off = 0.5f / 9.0f;
                reg_sum += (d0 <= th) ? 4.5f * d0 * d0 : d0 - off;
                reg_sum += (d1 <= th) ? 4.5f * d1 * d1 : d1 - off;
                reg_sum += (d2 <= th) ? 4.5f * d2 * d2 : d2 - off;
                reg_sum += (d3 <= th) ? 4.5f * d3 * d3 : d3 - off;

                // correction: replace negative-formula term with positive-formula
                // term for the single matched class of this anchor
                const float p = cls[((size_t)b * K + k) * NC + state];
                const float pos_t = COEF_POS * fsqrt_approx(1.0f - p) * flg2_approx(p);
                const float neg_t = COEF_NEG * fsqrt_approx(p) * flg2_approx(1.0f - p);
                cls_sum = pos_t - neg_t;
            } else {
                state = (best < 0.4f) ? -1 : -2;
            }
        }
        s_w[tid] = (state != -2) ? COEF_NEG : 0.0f;
    }
    __syncthreads();

    // ---- classification sweep: negative formula for every non-ignored element,
    //      branchless, fully coalesced float4 reads ----
    const float4* cp   = (const float4*)cls + (size_t)b * K * C4N;
    const int     gb   = s * C4N;
    const int     gmax = K * C4N - 1;
    #pragma unroll 5
    for (int it = 0; it < C4N; it++) {
        const int rel = it * APB + tid;
        const int al  = rel / C4N;             // local anchor for weight
        int g = gb + rel;
        g = (g < gmax) ? g : gmax;             // clamp: safe load, weight is 0 there
        const float  w = s_w[al];
        const float4 v = cp[g];
        cls_sum = fmaf(w, fsqrt_approx(v.x) * flg2_approx(1.0f - v.x), cls_sum);
        cls_sum = fmaf(w, fsqrt_approx(v.y) * flg2_approx(1.0f - v.y), cls_sum);
        cls_sum = fmaf(w, fsqrt_approx(v.z) * flg2_approx(1.0f - v.z), cls_sum);
        cls_sum = fmaf(w, fsqrt_approx(v.w) * flg2_approx(1.0f - v.w), cls_sum);
    }

    // ---- block reduction ----
    #pragma unroll
    for (int o = 16; o > 0; o >>= 1) {
        cls_sum += __shfl_down_sync(0xffffffffu, cls_sum, o);
        reg_sum += __shfl_down_sync(0xffffffffu, reg_sum, o);
        npos    += __shfl_down_sync(0xffffffffu, npos, o);
    }
    const int w = tid >> 5, l = tid & 31;
    if (l == 0) { s_red[0][w] = cls_sum; s_red[1][w] = reg_sum; s_red[2][w] = npos; }
    __syncthreads();

    if (tid == 0) {
        float c = 0.0f, r = 0.0f, n = 0.0f;
        #pragma unroll
        for (int i = 0; i < APB / 32; i++) { c += s_red[0][i]; r += s_red[1][i]; n += s_red[2][i]; }
        atomicAdd(&g_acc[b*3+0], c);
        atomicAdd(&g_acc[b*3+1], r);
        atomicAdd(&g_acc[b*3+2], n);
        __threadfence();

        const unsigned int total = gridDim.x * gridDim.y;
        const unsigned int old = atomicAdd(&g_count, 1u);
        if (old == total - 1u) {
            float cs = 0.0f, rs = 0.0f;
            for (int bb = 0; bb < B; bb++) {
                const float acc_c = atomicAdd(&g_acc[bb*3+0], 0.0f);
                const float acc_r = atomicAdd(&g_acc[bb*3+1], 0.0f);
                const float np    = atomicAdd(&g_acc[bb*3+2], 0.0f);
                cs += acc_c / fmaxf(np, 1.0f);
                rs += (np > 0.0f) ? acc_r / fmaxf(np * 4.0f, 1.0f) : 0.0f;
            }
            out[0] = cs / (float)B;
            out[1] = rs / (float)B;
            for (int i = 0; i < B * 3; i++) g_acc[i] = 0.0f;
            __threadfence();
            g_count = 0u;
            __threadfence();
        }
    }
}

extern "C" void kernel_launch(void* const* d_in, const int* in_sizes, int n_in,
                              void* d_out, int out_size) {
    const float* cls  = (const float*)d_in[0];   // [B,K,C]
    const float* regs = (const float*)d_in[1];   // [B,K,4]
    const float* anc  = (const float*)d_in[2];   // [1,K,4]
    const float* ann  = (const float*)d_in[3];   // [B,NANN,5]

    const int K = in_sizes[2] / 4;
    const int B = in_sizes[3] / (NANN * 5);

    dim3 grid((K + APB - 1) / APB, B);
    focal_fused_kernel<<<grid, APB>>>(cls, regs, anc, ann, (float*)d_out, K, B);
}

// round 4
// speedup vs baseline: 4.0092x; 1.5933x over previous
#include <cuda_runtime.h>

#define TPB 320      // threads per block == anchors per block (16*20)
#define NANN 32
#define NC 80
#define C4N 20       // float4 per anchor
#define MAXB 16

__device__ float g_acc[MAXB * 3];        // per image: cls_sum, reg_sum, num_pos
__device__ unsigned int g_count = 0;     // completed-block counter (self-resetting)

__device__ __forceinline__ float fsqrt_approx(float x) {
    float r;
    asm("sqrt.approx.f32 %0, %1;" : "=f"(r) : "f"(x));
    return r;
}
__device__ __forceinline__ float flg2_approx(float x) {
    float r;
    asm("lg2.approx.f32 %0, %1;" : "=f"(r) : "f"(x));
    return r;
}

__global__ __launch_bounds__(TPB) void focal_fused_kernel(
    const float* __restrict__ cls,     // [B,K,C]
    const float* __restrict__ regs,    // [B,K,4]
    const float* __restrict__ anc,     // [1,K,4]
    const float* __restrict__ ann,     // [B,NANN,5]
    float* __restrict__ out,
    int K, int B)
{
    const int b   = blockIdx.y;
    const int s   = blockIdx.x * TPB;
    const int tid = threadIdx.x;

    __shared__ float s_ann[NANN * 5];
    __shared__ float s_area[NANN];
    __shared__ float s_w[TPB];          // per-anchor sweep weight: 0 or COEF_NEG
    __shared__ float s_red[3][TPB / 32];

    if (tid < NANN * 5) s_ann[tid] = ann[(size_t)b * NANN * 5 + tid];
    __syncthreads();
    if (tid < NANN) {
        float x1 = s_ann[tid*5+0], y1 = s_ann[tid*5+1];
        float x2 = s_ann[tid*5+2], y2 = s_ann[tid*5+3];
        s_area[tid] = (x2 - x1) * (y2 - y1);
    }
    __syncthreads();

    const float LN2      = 0.6931471805599453f;
    const float COEF_NEG = -0.75f * LN2;   // term = COEF * sqrt(p) * lg2(1-p)
    const float COEF_POS = -0.25f * LN2;

    float reg_sum = 0.0f;
    float npos    = 0.0f;
    float corr    = 0.0f;    // positive-anchor class correction
    float wgt_me  = 0.0f;
    const int k   = s + tid;

    // ---------------- phase 1: IoU match (division-free) + reg loss ----------
    if (k < K) {
        const float4 av = *(const float4*)(anc + 4*(size_t)k);
        const float ax1 = av.x, ay1 = av.y, ax2 = av.z, ay2 = av.w;
        const float area_a = (ax2 - ax1) * (ay2 - ay1);

        // argmax of inter/uni via cross-multiplication (uni > 0 always)
        float best_in = -1.0f, best_un = 1.0f;
        int   bi = 0;
        #pragma unroll 8
        for (int n = 0; n < NANN; n++) {
            const float bx1 = s_ann[n*5+0], by1 = s_ann[n*5+1];
            const float bx2 = s_ann[n*5+2], by2 = s_ann[n*5+3];
            float iw = fmaxf(fminf(ax2, bx2) - fmaxf(ax1, bx1), 0.0f);
            float ih = fmaxf(fminf(ay2, by2) - fmaxf(ay1, by1), 0.0f);
            float inter = iw * ih;
            float uni   = fmaxf(area_a + s_area[n] - inter, 1e-8f);
            // strict > == first-argmax semantics
            if (inter * best_un > best_in * uni) {
                best_in = inter; best_un = uni; bi = n;
            }
        }

        const bool pos = (best_in >= 0.5f * best_un);
        const bool neg = (best_in <  0.4f * best_un);
        wgt_me = (pos || neg) ? COEF_NEG : 0.0f;   // ignored anchors weight 0

        if (pos) {
            npos = 1.0f;
            const int state = (int)s_ann[bi*5+4];
            const float aw  = ax2 - ax1, ah = ay2 - ay1;
            const float acx = ax1 + 0.5f * aw, acy = ay1 + 0.5f * ah;
            const float gx1 = s_ann[bi*5+0], gy1 = s_ann[bi*5+1];
            const float gx2 = s_ann[bi*5+2], gy2 = s_ann[bi*5+3];
            const float gw  = fmaxf(gx2 - gx1, 1.0f);
            const float gh  = fmaxf(gy2 - gy1, 1.0f);
            const float gcx = gx1 + 0.5f * gw, gcy = gy1 + 0.5f * gh;
            float t0 = (gcx - acx) / aw * 10.0f;
            float t1 = (gcy - acy) / ah * 10.0f;
            float t2 = __logf(gw / aw) * 5.0f;
            float t3 = __logf(gh / ah) * 5.0f;
            const float4 r = *(const float4*)(regs + ((size_t)b * K + k) * 4);
            float d0 = fabsf(t0 - r.x), d1 = fabsf(t1 - r.y);
            float d2 = fabsf(t2 - r.z), d3 = fabsf(t3 - r.w);
            const float th = 1.0f / 9.0f, off = 0.5f / 9.0f;
            reg_sum += (d0 <= th) ? 4.5f * d0 * d0 : d0 - off;
            reg_sum += (d1 <= th) ? 4.5f * d1 * d1 : d1 - off;
            reg_sum += (d2 <= th) ? 4.5f * d2 * d2 : d2 - off;
            reg_sum += (d3 <= th) ? 4.5f * d3 * d3 : d3 - off;

            // swap negative-formula term for positive-formula term (matched class)
            const float p = cls[((size_t)b * K + k) * NC + state];
            corr = COEF_POS * fsqrt_approx(1.0f - p) * flg2_approx(p)
                 - COEF_NEG * fsqrt_approx(p) * flg2_approx(1.0f - p);
        }
    }
    s_w[tid] = wgt_me;
    __syncthreads();

    // ---------------- phase 2: classification sweep ---------------------------
    // layout: 320 threads over 320 anchors x 20 float4; al = it*16 + tid/20
    // (division hoisted out of the loop), fully coalesced float4 reads.
    const float4* cp = (const float4*)cls + (size_t)b * K * C4N;
    const int a_div  = tid / 20;          // computed once
    const int gmax   = K * C4N - 1;
    int g = s * C4N + tid;

    float a0 = 0.0f, a1 = 0.0f, a2 = 0.0f, a3 = 0.0f;
    #pragma unroll 5
    for (int it = 0; it < C4N; it++) {
        const float w  = s_w[it * 16 + a_div];
        const int   gi = (g < gmax) ? g : gmax;   // OOB anchors have weight 0
        const float4 v = cp[gi];
        a0 = fmaf(w, fsqrt_approx(v.x) * flg2_approx(1.0f - v.x), a0);
        a1 = fmaf(w, fsqrt_approx(v.y) * flg2_approx(1.0f - v.y), a1);
        a2 = fmaf(w, fsqrt_approx(v.z) * flg2_approx(1.0f - v.z), a2);
        a3 = fmaf(w, fsqrt_approx(v.w) * flg2_approx(1.0f - v.w), a3);
        g += TPB;
    }
    float cls_sum = ((a0 + a1) + (a2 + a3)) + corr;

    // ---------------- block reduction -----------------------------------------
    #pragma unroll
    for (int o = 16; o > 0; o >>= 1) {
        cls_sum += __shfl_down_sync(0xffffffffu, cls_sum, o);
        reg_sum += __shfl_down_sync(0xffffffffu, reg_sum, o);
        npos    += __shfl_down_sync(0xffffffffu, npos, o);
    }
    const int w = tid >> 5, l = tid & 31;
    if (l == 0) { s_red[0][w] = cls_sum; s_red[1][w] = reg_sum; s_red[2][w] = npos; }
    __syncthreads();

    if (tid == 0) {
        float c = 0.0f, r = 0.0f, n = 0.0f;
        #pragma unroll
        for (int i = 0; i < TPB / 32; i++) { c += s_red[0][i]; r += s_red[1][i]; n += s_red[2][i]; }
        atomicAdd(&g_acc[b*3+0], c);
        atomicAdd(&g_acc[b*3+1], r);
        atomicAdd(&g_acc[b*3+2], n);
        __threadfence();

        const unsigned int total = gridDim.x * gridDim.y;
        const unsigned int old = atomicAdd(&g_count, 1u);
        if (old == total - 1u) {
            float cs = 0.0f, rs = 0.0f;
            for (int bb = 0; bb < B; bb++) {
                const float acc_c = atomicAdd(&g_acc[bb*3+0], 0.0f);
                const float acc_r = atomicAdd(&g_acc[bb*3+1], 0.0f);
                const float np    = atomicAdd(&g_acc[bb*3+2], 0.0f);
                cs += acc_c / fmaxf(np, 1.0f);
                rs += (np > 0.0f) ? acc_r / fmaxf(np * 4.0f, 1.0f) : 0.0f;
            }
            out[0] = cs / (float)B;
            out[1] = rs / (float)B;
            for (int i = 0; i < B * 3; i++) g_acc[i] = 0.0f;
            __threadfence();
            g_count = 0u;
            __threadfence();
        }
    }
}

extern "C" void kernel_launch(void* const* d_in, const int* in_sizes, int n_in,
                              void* d_out, int out_size) {
    const float* cls  = (const float*)d_in[0];   // [B,K,C]
    const float* regs = (const float*)d_in[1];   // [B,K,4]
    const float* anc  = (const float*)d_in[2];   // [1,K,4]
    const float* ann  = (const float*)d_in[3];   // [B,NANN,5]

    const int K = in_sizes[2] / 4;
    const int B = in_sizes[3] / (NANN * 5);

    dim3 grid((K + TPB - 1) / TPB, B);
    focal_fused_kernel<<<grid, TPB>>>(cls, regs, anc, ann, (float*)d_out, K, B);
}